// round 5
// baseline (speedup 1.0000x reference)
#include <cuda_runtime.h>
#include <cuda_fp16.h>
#include <cstdint>

#define N_NODES 50000
#define N_EDGES 1600000
#define N_FEAT  256
#define N_HID   128
#define N_CLASS 64

#define SCAN_B 1024
#define NBLK_SCAN ((N_NODES + SCAN_B - 1) / SCAN_B)   // 49

// ---------------- device scratch (static, no allocations) ----------------
__device__ float g_deg[N_NODES];
__device__ float g_dinv[N_NODES];
__device__ int   g_cnt[N_NODES];
__device__ int   g_scan_tmp[N_NODES];
__device__ int   g_partials[64];
__device__ int   g_rowptr[N_NODES + 1];
__device__ int   g_loc[N_EDGES];            // per-edge local slot within its dest segment
__device__ int2  g_csr[N_EDGES];            // packed (src, __float_as_int(norm))
// intermediates: GEMM outputs stored fp16 (gather bandwidth), h kept fp32 (GEMM2 input)
__device__ half2  g_xwh[(size_t)N_NODES * (N_HID / 2)];    // x @ W1  [N,128] fp16
__device__ float4 g_h4 [(size_t)N_NODES * (N_HID / 4)];    // sigmoid(.) [N,128] fp32
__device__ half2  g_hwh[(size_t)N_NODES * (N_CLASS / 2)];  // h @ W2  [N,64] fp16

// ---------------- prep kernels ----------------
__global__ void k_init() {
    int i = blockIdx.x * blockDim.x + threadIdx.x;
    if (i < N_NODES) { g_deg[i] = 1.0f; g_cnt[i] = 0; }   // self-loop weight 1
}

__global__ void k_deg(const int* __restrict__ ei, const float* __restrict__ ew) {
    int e = blockIdx.x * blockDim.x + threadIdx.x;
    if (e < N_EDGES) {
        int c = ei[N_EDGES + e];
        if ((unsigned)c < N_NODES) {
            atomicAdd(&g_deg[c], ew[e]);
            g_loc[e] = atomicAdd(&g_cnt[c], 1);
        }
    }
}

__global__ void k_scan1() {   // block-inclusive scan of cnt; also computes dinv
    __shared__ int s[SCAN_B];
    int i = blockIdx.x * SCAN_B + threadIdx.x;
    if (i < N_NODES) {
        float d = g_deg[i];
        g_dinv[i] = (d > 0.f) ? rsqrtf(d) : 0.f;
    }
    int v = (i < N_NODES) ? g_cnt[i] : 0;
    s[threadIdx.x] = v;
    __syncthreads();
    for (int off = 1; off < SCAN_B; off <<= 1) {
        int t = (threadIdx.x >= off) ? s[threadIdx.x - off] : 0;
        __syncthreads();
        s[threadIdx.x] += t;
        __syncthreads();
    }
    if (i < N_NODES) g_scan_tmp[i] = s[threadIdx.x];      // inclusive
    if (threadIdx.x == SCAN_B - 1) g_partials[blockIdx.x] = s[SCAN_B - 1];
}

__global__ void k_scan2() {
    __shared__ int s[64];
    int t = threadIdx.x;
    int v = (t < NBLK_SCAN) ? g_partials[t] : 0;
    s[t] = v;
    __syncthreads();
    for (int off = 1; off < 64; off <<= 1) {
        int u = (t >= off) ? s[t - off] : 0;
        __syncthreads();
        s[t] += u;
        __syncthreads();
    }
    if (t < NBLK_SCAN) g_partials[t] = s[t] - v;          // exclusive
}

__global__ void k_scan3() {
    int i = blockIdx.x * SCAN_B + threadIdx.x;
    if (i < N_NODES) {
        g_rowptr[i] = g_scan_tmp[i] - g_cnt[i] + g_partials[blockIdx.x];
    }
    if (i == 0) g_rowptr[N_NODES] = N_EDGES;
}

__global__ void k_scatter(const int* __restrict__ ei, const float* __restrict__ ew) {
    int e = blockIdx.x * blockDim.x + threadIdx.x;
    if (e < N_EDGES) {
        int r = ei[e];
        int c = ei[N_EDGES + e];
        if ((unsigned)r < N_NODES && (unsigned)c < N_NODES) {
            float nrm = g_dinv[r] * ew[e] * g_dinv[c];
            int p = g_rowptr[c] + g_loc[e];          // atomic-free placement
            g_csr[p] = make_int2(r, __float_as_int(nrm));
        }
    }
}

// ---------------- fp32 register-tiled GEMM, fp16 epilogue ----------------
// LAYER 0: g_xwh = x(param) @ W1   (K=256, NO=128, TM=8, TN=8)
// LAYER 1: g_hwh = g_h @ W2        (K=128, NO=64,  TM=8, TN=4)
template<int K, int NO, int TM, int TN, int LAYER>
__global__ __launch_bounds__(256) void k_gemm(const float* __restrict__ Ain,
                                              const float* __restrict__ B, int M) {
    const float* __restrict__ A = (LAYER == 0) ? Ain : (const float*)g_h4;
    half2* __restrict__ C = (LAYER == 0) ? g_xwh : g_hwh;

    constexpr int BK = 16;
    constexpr int NX = NO / TN;              // 16 column groups
    constexpr int NY = 256 / NX;             // 16 row groups
    constexpr int BM = NY * TM;              // 128
    constexpr int CNT_A = BM * BK / (4 * 256);   // float4 A-loads per thread (=2)
    constexpr int CNT_B = BK * NO / (4 * 256);   // float4 B-loads per thread (2 or 1)

    __shared__ float As[BK][BM];             // A tile, transposed
    __shared__ float Bs[BK][NO];

    const int tid = threadIdx.x;
    const int bm  = blockIdx.x * BM;
    const int tx  = tid % NX;
    const int ty  = tid / NX;

    float acc[TM][TN];
    #pragma unroll
    for (int i = 0; i < TM; i++)
        #pragma unroll
        for (int j = 0; j < TN; j++) acc[i][j] = 0.f;

    for (int k0 = 0; k0 < K; k0 += BK) {
        #pragma unroll
        for (int i = 0; i < CNT_A; i++) {
            int t  = tid + i * 256;
            int r  = t >> 2;
            int c4 = (t & 3) << 2;
            float4 v = make_float4(0.f, 0.f, 0.f, 0.f);
            if (bm + r < M)
                v = *(const float4*)(A + (size_t)(bm + r) * K + k0 + c4);
            As[c4 + 0][r] = v.x; As[c4 + 1][r] = v.y;
            As[c4 + 2][r] = v.z; As[c4 + 3][r] = v.w;
        }
        #pragma unroll
        for (int i = 0; i < CNT_B; i++) {
            int t  = tid + i * 256;
            int r  = t / (NO / 4);
            int c4 = (t % (NO / 4)) << 2;
            *(float4*)&Bs[r][c4] = *(const float4*)(B + (size_t)(k0 + r) * NO + c4);
        }
        __syncthreads();

        #pragma unroll
        for (int k = 0; k < BK; k++) {
            float a[TM], b[TN];
            #pragma unroll
            for (int i = 0; i < TM; i += 4) {
                float4 a4 = *(const float4*)&As[k][ty * TM + i];
                a[i] = a4.x; a[i+1] = a4.y; a[i+2] = a4.z; a[i+3] = a4.w;
            }
            #pragma unroll
            for (int j = 0; j < TN; j += 4) {
                float4 b4 = *(const float4*)&Bs[k][tx * TN + j];
                b[j] = b4.x; b[j+1] = b4.y; b[j+2] = b4.z; b[j+3] = b4.w;
            }
            #pragma unroll
            for (int i = 0; i < TM; i++)
                #pragma unroll
                for (int j = 0; j < TN; j++)
                    acc[i][j] = fmaf(a[i], b[j], acc[i][j]);
        }
        __syncthreads();
    }

    #pragma unroll
    for (int i = 0; i < TM; i++) {
        int r = bm + ty * TM + i;
        if (r < M) {
            if constexpr (TN == 8) {
                half2 p0 = __floats2half2_rn(acc[i][0], acc[i][1]);
                half2 p1 = __floats2half2_rn(acc[i][2], acc[i][3]);
                half2 p2 = __floats2half2_rn(acc[i][4], acc[i][5]);
                half2 p3 = __floats2half2_rn(acc[i][6], acc[i][7]);
                uint4 u;
                u.x = *(unsigned*)&p0; u.y = *(unsigned*)&p1;
                u.z = *(unsigned*)&p2; u.w = *(unsigned*)&p3;
                *(uint4*)(C + (size_t)r * (NO / 2) + tx * 4) = u;
            } else {  // TN == 4
                half2 p0 = __floats2half2_rn(acc[i][0], acc[i][1]);
                half2 p1 = __floats2half2_rn(acc[i][2], acc[i][3]);
                uint2 u;
                u.x = *(unsigned*)&p0; u.y = *(unsigned*)&p1;
                *(uint2*)(C + (size_t)r * (NO / 2) + tx * 2) = u;
            }
        }
    }
}

// ---------------- gather-based aggregation (fp16 gather, fp32 accumulate) ----------------
// out[c,:] = act( sum_{e:col=c} norm_e * hin[src_e,:] + dinv[c]^2 * hin[c,:] + bias )
template<int F, int LAYER>
__global__ __launch_bounds__(256) void k_agg(const float* __restrict__ bias,
                                             float* __restrict__ out_param) {
    int gw   = (blockIdx.x * blockDim.x + threadIdx.x) >> 5;
    int lane = threadIdx.x & 31;
    if (gw >= N_NODES) return;
    const int c = gw;
    const int e0 = g_rowptr[c];
    const int e1 = g_rowptr[c + 1];
    const int2* __restrict__ csr = g_csr;

    if constexpr (F == 128) {
        // row = 64 half2 = 32 uint2; lane covers features lane*4 .. lane*4+3
        const uint2* __restrict__ hv = (const uint2*)g_xwh;
        float4 acc = make_float4(0.f, 0.f, 0.f, 0.f);
        int p = e0;
        for (; p + 4 <= e1; p += 4) {           // 4 independent gathers in flight
            int2 s0 = csr[p], s1 = csr[p+1], s2 = csr[p+2], s3 = csr[p+3];
            uint2 q0 = hv[(size_t)s0.x * 32 + lane];
            uint2 q1 = hv[(size_t)s1.x * 32 + lane];
            uint2 q2 = hv[(size_t)s2.x * 32 + lane];
            uint2 q3 = hv[(size_t)s3.x * 32 + lane];
            float w0 = __int_as_float(s0.y), w1 = __int_as_float(s1.y);
            float w2 = __int_as_float(s2.y), w3 = __int_as_float(s3.y);
            float2 a0 = __half22float2(*(half2*)&q0.x), b0 = __half22float2(*(half2*)&q0.y);
            float2 a1 = __half22float2(*(half2*)&q1.x), b1 = __half22float2(*(half2*)&q1.y);
            float2 a2 = __half22float2(*(half2*)&q2.x), b2 = __half22float2(*(half2*)&q2.y);
            float2 a3 = __half22float2(*(half2*)&q3.x), b3 = __half22float2(*(half2*)&q3.y);
            acc.x = fmaf(w0, a0.x, acc.x); acc.y = fmaf(w0, a0.y, acc.y);
            acc.z = fmaf(w0, b0.x, acc.z); acc.w = fmaf(w0, b0.y, acc.w);
            acc.x = fmaf(w1, a1.x, acc.x); acc.y = fmaf(w1, a1.y, acc.y);
            acc.z = fmaf(w1, b1.x, acc.z); acc.w = fmaf(w1, b1.y, acc.w);
            acc.x = fmaf(w2, a2.x, acc.x); acc.y = fmaf(w2, a2.y, acc.y);
            acc.z = fmaf(w2, b2.x, acc.z); acc.w = fmaf(w2, b2.y, acc.w);
            acc.x = fmaf(w3, a3.x, acc.x); acc.y = fmaf(w3, a3.y, acc.y);
            acc.z = fmaf(w3, b3.x, acc.z); acc.w = fmaf(w3, b3.y, acc.w);
        }
        for (; p < e1; p++) {
            int2 s = csr[p];
            float w = __int_as_float(s.y);
            uint2 q = hv[(size_t)s.x * 32 + lane];
            float2 a = __half22float2(*(half2*)&q.x), b = __half22float2(*(half2*)&q.y);
            acc.x = fmaf(w, a.x, acc.x); acc.y = fmaf(w, a.y, acc.y);
            acc.z = fmaf(w, b.x, acc.z); acc.w = fmaf(w, b.y, acc.w);
        }
        float di = g_dinv[c];
        float sw = di * di;
        uint2 q = hv[(size_t)c * 32 + lane];
        float2 a = __half22float2(*(half2*)&q.x), b = __half22float2(*(half2*)&q.y);
        acc.x = fmaf(sw, a.x, acc.x); acc.y = fmaf(sw, a.y, acc.y);
        acc.z = fmaf(sw, b.x, acc.z); acc.w = fmaf(sw, b.y, acc.w);
        float4 bb = ((const float4*)bias)[lane];
        acc.x += bb.x; acc.y += bb.y; acc.z += bb.z; acc.w += bb.w;
        acc.x = 1.f / (1.f + __expf(-acc.x));
        acc.y = 1.f / (1.f + __expf(-acc.y));
        acc.z = 1.f / (1.f + __expf(-acc.z));
        acc.w = 1.f / (1.f + __expf(-acc.w));
        g_h4[(size_t)c * 32 + lane] = acc;      // fp32 for GEMM2 input
    } else {  // F == 64
        // row = 32 half2; lane covers features lane*2 .. lane*2+1
        const unsigned* __restrict__ hv = (const unsigned*)g_hwh;
        float2 acc = make_float2(0.f, 0.f);
        int p = e0;
        for (; p + 4 <= e1; p += 4) {
            int2 s0 = csr[p], s1 = csr[p+1], s2 = csr[p+2], s3 = csr[p+3];
            unsigned q0 = hv[(size_t)s0.x * 32 + lane];
            unsigned q1 = hv[(size_t)s1.x * 32 + lane];
            unsigned q2 = hv[(size_t)s2.x * 32 + lane];
            unsigned q3 = hv[(size_t)s3.x * 32 + lane];
            float w0 = __int_as_float(s0.y), w1 = __int_as_float(s1.y);
            float w2 = __int_as_float(s2.y), w3 = __int_as_float(s3.y);
            float2 v0 = __half22float2(*(half2*)&q0);
            float2 v1 = __half22float2(*(half2*)&q1);
            float2 v2 = __half22float2(*(half2*)&q2);
            float2 v3 = __half22float2(*(half2*)&q3);
            acc.x = fmaf(w0, v0.x, acc.x); acc.y = fmaf(w0, v0.y, acc.y);
            acc.x = fmaf(w1, v1.x, acc.x); acc.y = fmaf(w1, v1.y, acc.y);
            acc.x = fmaf(w2, v2.x, acc.x); acc.y = fmaf(w2, v2.y, acc.y);
            acc.x = fmaf(w3, v3.x, acc.x); acc.y = fmaf(w3, v3.y, acc.y);
        }
        for (; p < e1; p++) {
            int2 s = csr[p];
            float w = __int_as_float(s.y);
            unsigned q = hv[(size_t)s.x * 32 + lane];
            float2 v = __half22float2(*(half2*)&q);
            acc.x = fmaf(w, v.x, acc.x);
            acc.y = fmaf(w, v.y, acc.y);
        }
        float di = g_dinv[c];
        float sw = di * di;
        unsigned q = hv[(size_t)c * 32 + lane];
        float2 v = __half22float2(*(half2*)&q);
        acc.x = fmaf(sw, v.x, acc.x);
        acc.y = fmaf(sw, v.y, acc.y);
        float2 bb = ((const float2*)bias)[lane];
        acc.x += bb.x; acc.y += bb.y;
        acc.x = tanhf(acc.x);
        acc.y = tanhf(acc.y);
        ((float2*)out_param)[(size_t)c * 32 + lane] = acc;
    }
}

// ---------------- launch ----------------
extern "C" void kernel_launch(void* const* d_in, const int* in_sizes, int n_in,
                              void* d_out, int out_size) {
    const float* x  = (const float*)d_in[0];
    const int*   ei = (const int*)d_in[1];     // int32 edge_index (2, E) row-major
    const float* ew = (const float*)d_in[2];
    const float* W1 = (const float*)d_in[3];
    const float* b1 = (const float*)d_in[4];
    const float* W2 = (const float*)d_in[5];
    const float* b2 = (const float*)d_in[6];
    float*       out = (float*)d_out;

    const int TB = 256;
    const int nblk_nodes = (N_NODES + TB - 1) / TB;       // 196
    const int nblk_edges = (N_EDGES + TB - 1) / TB;       // 6250
    const int nblk_warp  = (N_NODES * 32 + TB - 1) / TB;  // 6250

    // ---- normalization + CSR build ----
    k_init <<<nblk_nodes, TB>>>();
    k_deg  <<<nblk_edges, TB>>>(ei, ew);
    k_scan1<<<NBLK_SCAN, SCAN_B>>>();
    k_scan2<<<1, 64>>>();
    k_scan3<<<NBLK_SCAN, SCAN_B>>>();
    k_scatter<<<nblk_edges, TB>>>(ei, ew);

    // ---- layer 1 ----
    k_gemm<N_FEAT, N_HID, 8, 8, 0><<<(N_NODES + 127) / 128, 256>>>(x, W1, N_NODES);
    k_agg<N_HID, 0><<<nblk_warp, TB>>>(b1, nullptr);

    // ---- layer 2 ----
    k_gemm<N_HID, N_CLASS, 8, 4, 1><<<(N_NODES + 127) / 128, 256>>>(nullptr, W2, N_NODES);
    k_agg<N_CLASS, 1><<<nblk_warp, TB>>>(b2, out);
}

// round 6
// speedup vs baseline: 1.1049x; 1.1049x over previous
#include <cuda_runtime.h>
#include <cuda_fp16.h>
#include <cstdint>

#define N_NODES 50000
#define N_EDGES 1600000
#define N_FEAT  256
#define N_HID   128
#define N_CLASS 64

#define SCAN_B 1024
#define NBLK_SCAN ((N_NODES + SCAN_B - 1) / SCAN_B)   // 49

// ---------------- device scratch (static, no allocations) ----------------
// g_deg / g_cnt: zero at module load; every kernel_launch leaves them zeroed
// again (scan1 zeroes deg after reading, scan3 zeroes cnt after reading), so
// each graph replay starts from the same state. Deterministic.
__device__ float g_deg[N_NODES];
__device__ float g_dinv[N_NODES];
__device__ int   g_cnt[N_NODES];
__device__ int   g_scan_tmp[N_NODES];
__device__ int   g_partials[64];
__device__ int   g_rowptr[N_NODES + 1];
__device__ int   g_loc[N_EDGES];            // per-edge local slot within its dest segment
__device__ int2  g_csr[N_EDGES];            // packed (src, __float_as_int(norm))
// intermediates: GEMM outputs stored fp16 (gather bandwidth), h kept fp32 (GEMM2 input)
__device__ half2  g_xwh[(size_t)N_NODES * (N_HID / 2)];    // x @ W1  [N,128] fp16
__device__ float4 g_h4 [(size_t)N_NODES * (N_HID / 4)];    // sigmoid(.) [N,128] fp32
__device__ half2  g_hwh[(size_t)N_NODES * (N_CLASS / 2)];  // h @ W2  [N,64] fp16

// ---------------- f32x2 packed-FMA helpers (sm_103a FFMA2, PTX-only) ----------------
__device__ __forceinline__ unsigned long long pack_dup(float a) {
    unsigned long long r;
    unsigned u = __float_as_uint(a);
    asm("mov.b64 %0, {%1, %1};" : "=l"(r) : "r"(u));
    return r;
}
__device__ __forceinline__ void fma2(unsigned long long& acc,
                                     unsigned long long a, unsigned long long b) {
    asm("fma.rn.f32x2 %0, %1, %2, %0;" : "+l"(acc) : "l"(a), "l"(b));
}
__device__ __forceinline__ float2 unpack2(unsigned long long v) {
    unsigned lo, hi;
    asm("mov.b64 {%0, %1}, %2;" : "=r"(lo), "=r"(hi) : "l"(v));
    return make_float2(__uint_as_float(lo), __uint_as_float(hi));
}

// ---------------- prep kernels ----------------
__global__ void k_deg(const int* __restrict__ ei, const float* __restrict__ ew) {
    int e = blockIdx.x * blockDim.x + threadIdx.x;
    if (e < N_EDGES) {
        int c = ei[N_EDGES + e];
        if ((unsigned)c < N_NODES) {
            atomicAdd(&g_deg[c], ew[e]);
            g_loc[e] = atomicAdd(&g_cnt[c], 1);
        }
    }
}

__global__ void k_scan1() {   // block-inclusive scan of cnt; dinv; self-clean deg
    __shared__ int s[SCAN_B];
    int i = blockIdx.x * SCAN_B + threadIdx.x;
    if (i < N_NODES) {
        float d = g_deg[i];
        g_dinv[i] = rsqrtf(d + 1.0f);   // +1 = self-loop weight
        g_deg[i] = 0.0f;                // restore invariant for next replay
    }
    int v = (i < N_NODES) ? g_cnt[i] : 0;
    s[threadIdx.x] = v;
    __syncthreads();
    for (int off = 1; off < SCAN_B; off <<= 1) {
        int t = (threadIdx.x >= off) ? s[threadIdx.x - off] : 0;
        __syncthreads();
        s[threadIdx.x] += t;
        __syncthreads();
    }
    if (i < N_NODES) g_scan_tmp[i] = s[threadIdx.x];      // inclusive
    if (threadIdx.x == SCAN_B - 1) g_partials[blockIdx.x] = s[SCAN_B - 1];
}

__global__ void k_scan2() {
    __shared__ int s[64];
    int t = threadIdx.x;
    int v = (t < NBLK_SCAN) ? g_partials[t] : 0;
    s[t] = v;
    __syncthreads();
    for (int off = 1; off < 64; off <<= 1) {
        int u = (t >= off) ? s[t - off] : 0;
        __syncthreads();
        s[t] += u;
        __syncthreads();
    }
    if (t < NBLK_SCAN) g_partials[t] = s[t] - v;          // exclusive
}

__global__ void k_scan3() {
    int i = blockIdx.x * SCAN_B + threadIdx.x;
    if (i < N_NODES) {
        g_rowptr[i] = g_scan_tmp[i] - g_cnt[i] + g_partials[blockIdx.x];
        g_cnt[i] = 0;                   // restore invariant for next replay
    }
    if (i == 0) g_rowptr[N_NODES] = N_EDGES;
}

__global__ void k_scatter(const int* __restrict__ ei, const float* __restrict__ ew) {
    int e = blockIdx.x * blockDim.x + threadIdx.x;
    if (e < N_EDGES) {
        int r = ei[e];
        int c = ei[N_EDGES + e];
        if ((unsigned)r < N_NODES && (unsigned)c < N_NODES) {
            float nrm = g_dinv[r] * ew[e] * g_dinv[c];
            int p = g_rowptr[c] + g_loc[e];          // atomic-free placement
            g_csr[p] = make_int2(r, __float_as_int(nrm));
        }
    }
}

// ---------------- f32x2-packed register-tiled GEMM, fp16 epilogue ----------------
// LAYER 0: g_xwh = x(param) @ W1   (K=256, NO=128, TM=8, TN=8)
// LAYER 1: g_hwh = g_h @ W2        (K=128, NO=64,  TM=8, TN=4)
template<int K, int NO, int TM, int TN, int LAYER>
__global__ __launch_bounds__(256) void k_gemm(const float* __restrict__ Ain,
                                              const float* __restrict__ B, int M) {
    const float* __restrict__ A = (LAYER == 0) ? Ain : (const float*)g_h4;
    half2* __restrict__ C = (LAYER == 0) ? g_xwh : g_hwh;

    constexpr int BK = 16;
    constexpr int NX = NO / TN;              // 16 column groups
    constexpr int NY = 256 / NX;             // 16 row groups
    constexpr int BM = NY * TM;              // 128
    constexpr int TP = TN / 2;               // f32x2 pairs per row
    constexpr int CNT_A = BM * BK / (4 * 256);   // float4 A-loads per thread (=2)
    constexpr int CNT_B = BK * NO / (4 * 256);   // float4 B-loads per thread (2 or 1)

    __shared__ float As[BK][BM];             // A tile, transposed
    __shared__ float Bs[BK][NO];

    const int tid = threadIdx.x;
    const int bm  = blockIdx.x * BM;
    const int tx  = tid % NX;
    const int ty  = tid / NX;

    unsigned long long acc[TM][TP];
    #pragma unroll
    for (int i = 0; i < TM; i++)
        #pragma unroll
        for (int j = 0; j < TP; j++) acc[i][j] = 0ull;   // bits 0 == (0.f, 0.f)

    for (int k0 = 0; k0 < K; k0 += BK) {
        #pragma unroll
        for (int i = 0; i < CNT_A; i++) {
            int t  = tid + i * 256;
            int r  = t >> 2;
            int c4 = (t & 3) << 2;
            float4 v = make_float4(0.f, 0.f, 0.f, 0.f);
            if (bm + r < M)
                v = *(const float4*)(A + (size_t)(bm + r) * K + k0 + c4);
            As[c4 + 0][r] = v.x; As[c4 + 1][r] = v.y;
            As[c4 + 2][r] = v.z; As[c4 + 3][r] = v.w;
        }
        #pragma unroll
        for (int i = 0; i < CNT_B; i++) {
            int t  = tid + i * 256;
            int r  = t / (NO / 4);
            int c4 = (t % (NO / 4)) << 2;
            *(float4*)&Bs[r][c4] = *(const float4*)(B + (size_t)(k0 + r) * NO + c4);
        }
        __syncthreads();

        #pragma unroll
        for (int k = 0; k < BK; k++) {
            // A: TM values, each duplicated into a 64-bit pair
            unsigned long long ap[TM];
            #pragma unroll
            for (int i = 0; i < TM; i += 4) {
                float4 a4 = *(const float4*)&As[k][ty * TM + i];
                ap[i]   = pack_dup(a4.x);
                ap[i+1] = pack_dup(a4.y);
                ap[i+2] = pack_dup(a4.z);
                ap[i+3] = pack_dup(a4.w);
            }
            // B: contiguous pairs, reinterpret shared float4 as two packed pairs
            unsigned long long bp[TP];
            #pragma unroll
            for (int j = 0; j < TP; j += 2) {
                ulonglong2 b2 = *(const ulonglong2*)&Bs[k][tx * TN + j * 2];
                bp[j]   = b2.x;
                bp[j+1] = b2.y;
            }
            #pragma unroll
            for (int i = 0; i < TM; i++)
                #pragma unroll
                for (int j = 0; j < TP; j++)
                    fma2(acc[i][j], ap[i], bp[j]);
        }
        __syncthreads();
    }

    #pragma unroll
    for (int i = 0; i < TM; i++) {
        int r = bm + ty * TM + i;
        if (r < M) {
            if constexpr (TP == 4) {
                float2 f0 = unpack2(acc[i][0]);
                float2 f1 = unpack2(acc[i][1]);
                float2 f2 = unpack2(acc[i][2]);
                float2 f3 = unpack2(acc[i][3]);
                half2 p0 = __floats2half2_rn(f0.x, f0.y);
                half2 p1 = __floats2half2_rn(f1.x, f1.y);
                half2 p2 = __floats2half2_rn(f2.x, f2.y);
                half2 p3 = __floats2half2_rn(f3.x, f3.y);
                uint4 u;
                u.x = *(unsigned*)&p0; u.y = *(unsigned*)&p1;
                u.z = *(unsigned*)&p2; u.w = *(unsigned*)&p3;
                *(uint4*)(C + (size_t)r * (NO / 2) + tx * 4) = u;
            } else {  // TP == 2
                float2 f0 = unpack2(acc[i][0]);
                float2 f1 = unpack2(acc[i][1]);
                half2 p0 = __floats2half2_rn(f0.x, f0.y);
                half2 p1 = __floats2half2_rn(f1.x, f1.y);
                uint2 u;
                u.x = *(unsigned*)&p0; u.y = *(unsigned*)&p1;
                *(uint2*)(C + (size_t)r * (NO / 2) + tx * 2) = u;
            }
        }
    }
}

// ---------------- gather-based aggregation (fp16 gather, fp32 accumulate) ----------------
template<int F, int LAYER>
__global__ __launch_bounds__(256) void k_agg(const float* __restrict__ bias,
                                             float* __restrict__ out_param) {
    int gw   = (blockIdx.x * blockDim.x + threadIdx.x) >> 5;
    int lane = threadIdx.x & 31;
    if (gw >= N_NODES) return;
    const int c = gw;
    const int e0 = g_rowptr[c];
    const int e1 = g_rowptr[c + 1];
    const int2* __restrict__ csr = g_csr;

    if constexpr (F == 128) {
        const uint2* __restrict__ hv = (const uint2*)g_xwh;
        float4 acc = make_float4(0.f, 0.f, 0.f, 0.f);
        int p = e0;
        for (; p + 4 <= e1; p += 4) {           // 4 independent gathers in flight
            int2 s0 = csr[p], s1 = csr[p+1], s2 = csr[p+2], s3 = csr[p+3];
            uint2 q0 = hv[(size_t)s0.x * 32 + lane];
            uint2 q1 = hv[(size_t)s1.x * 32 + lane];
            uint2 q2 = hv[(size_t)s2.x * 32 + lane];
            uint2 q3 = hv[(size_t)s3.x * 32 + lane];
            float w0 = __int_as_float(s0.y), w1 = __int_as_float(s1.y);
            float w2 = __int_as_float(s2.y), w3 = __int_as_float(s3.y);
            float2 a0 = __half22float2(*(half2*)&q0.x), b0 = __half22float2(*(half2*)&q0.y);
            float2 a1 = __half22float2(*(half2*)&q1.x), b1 = __half22float2(*(half2*)&q1.y);
            float2 a2 = __half22float2(*(half2*)&q2.x), b2 = __half22float2(*(half2*)&q2.y);
            float2 a3 = __half22float2(*(half2*)&q3.x), b3 = __half22float2(*(half2*)&q3.y);
            acc.x = fmaf(w0, a0.x, acc.x); acc.y = fmaf(w0, a0.y, acc.y);
            acc.z = fmaf(w0, b0.x, acc.z); acc.w = fmaf(w0, b0.y, acc.w);
            acc.x = fmaf(w1, a1.x, acc.x); acc.y = fmaf(w1, a1.y, acc.y);
            acc.z = fmaf(w1, b1.x, acc.z); acc.w = fmaf(w1, b1.y, acc.w);
            acc.x = fmaf(w2, a2.x, acc.x); acc.y = fmaf(w2, a2.y, acc.y);
            acc.z = fmaf(w2, b2.x, acc.z); acc.w = fmaf(w2, b2.y, acc.w);
            acc.x = fmaf(w3, a3.x, acc.x); acc.y = fmaf(w3, a3.y, acc.y);
            acc.z = fmaf(w3, b3.x, acc.z); acc.w = fmaf(w3, b3.y, acc.w);
        }
        for (; p < e1; p++) {
            int2 s = csr[p];
            float w = __int_as_float(s.y);
            uint2 q = hv[(size_t)s.x * 32 + lane];
            float2 a = __half22float2(*(half2*)&q.x), b = __half22float2(*(half2*)&q.y);
            acc.x = fmaf(w, a.x, acc.x); acc.y = fmaf(w, a.y, acc.y);
            acc.z = fmaf(w, b.x, acc.z); acc.w = fmaf(w, b.y, acc.w);
        }
        float di = g_dinv[c];
        float sw = di * di;
        uint2 q = hv[(size_t)c * 32 + lane];
        float2 a = __half22float2(*(half2*)&q.x), b = __half22float2(*(half2*)&q.y);
        acc.x = fmaf(sw, a.x, acc.x); acc.y = fmaf(sw, a.y, acc.y);
        acc.z = fmaf(sw, b.x, acc.z); acc.w = fmaf(sw, b.y, acc.w);
        float4 bb = ((const float4*)bias)[lane];
        acc.x += bb.x; acc.y += bb.y; acc.z += bb.z; acc.w += bb.w;
        acc.x = 1.f / (1.f + __expf(-acc.x));
        acc.y = 1.f / (1.f + __expf(-acc.y));
        acc.z = 1.f / (1.f + __expf(-acc.z));
        acc.w = 1.f / (1.f + __expf(-acc.w));
        g_h4[(size_t)c * 32 + lane] = acc;      // fp32 for GEMM2 input
    } else {  // F == 64
        const unsigned* __restrict__ hv = (const unsigned*)g_hwh;
        float2 acc = make_float2(0.f, 0.f);
        int p = e0;
        for (; p + 4 <= e1; p += 4) {
            int2 s0 = csr[p], s1 = csr[p+1], s2 = csr[p+2], s3 = csr[p+3];
            unsigned q0 = hv[(size_t)s0.x * 32 + lane];
            unsigned q1 = hv[(size_t)s1.x * 32 + lane];
            unsigned q2 = hv[(size_t)s2.x * 32 + lane];
            unsigned q3 = hv[(size_t)s3.x * 32 + lane];
            float w0 = __int_as_float(s0.y), w1 = __int_as_float(s1.y);
            float w2 = __int_as_float(s2.y), w3 = __int_as_float(s3.y);
            float2 v0 = __half22float2(*(half2*)&q0);
            float2 v1 = __half22float2(*(half2*)&q1);
            float2 v2 = __half22float2(*(half2*)&q2);
            float2 v3 = __half22float2(*(half2*)&q3);
            acc.x = fmaf(w0, v0.x, acc.x); acc.y = fmaf(w0, v0.y, acc.y);
            acc.x = fmaf(w1, v1.x, acc.x); acc.y = fmaf(w1, v1.y, acc.y);
            acc.x = fmaf(w2, v2.x, acc.x); acc.y = fmaf(w2, v2.y, acc.y);
            acc.x = fmaf(w3, v3.x, acc.x); acc.y = fmaf(w3, v3.y, acc.y);
        }
        for (; p < e1; p++) {
            int2 s = csr[p];
            float w = __int_as_float(s.y);
            unsigned q = hv[(size_t)s.x * 32 + lane];
            float2 v = __half22float2(*(half2*)&q);
            acc.x = fmaf(w, v.x, acc.x);
            acc.y = fmaf(w, v.y, acc.y);
        }
        float di = g_dinv[c];
        float sw = di * di;
        unsigned q = hv[(size_t)c * 32 + lane];
        float2 v = __half22float2(*(half2*)&q);
        acc.x = fmaf(sw, v.x, acc.x);
        acc.y = fmaf(sw, v.y, acc.y);
        float2 bb = ((const float2*)bias)[lane];
        acc.x += bb.x; acc.y += bb.y;
        acc.x = tanhf(acc.x);
        acc.y = tanhf(acc.y);
        ((float2*)out_param)[(size_t)c * 32 + lane] = acc;
    }
}

// ---------------- launch ----------------
extern "C" void kernel_launch(void* const* d_in, const int* in_sizes, int n_in,
                              void* d_out, int out_size) {
    const float* x  = (const float*)d_in[0];
    const int*   ei = (const int*)d_in[1];     // int32 edge_index (2, E) row-major
    const float* ew = (const float*)d_in[2];
    const float* W1 = (const float*)d_in[3];
    const float* b1 = (const float*)d_in[4];
    const float* W2 = (const float*)d_in[5];
    const float* b2 = (const float*)d_in[6];
    float*       out = (float*)d_out;

    const int TB = 256;
    const int nblk_edges = (N_EDGES + TB - 1) / TB;       // 6250
    const int nblk_warp  = (N_NODES * 32 + TB - 1) / TB;  // 6250

    // prep (deg/cnt start zero: zero at load, re-zeroed by scan1/scan3 each call)
    k_deg  <<<nblk_edges, TB>>>(ei, ew);
    k_scan1<<<NBLK_SCAN, SCAN_B>>>();
    k_scan2<<<1, 64>>>();
    // gemm1 is independent of the CSR build; placed here so the profiler's
    // fixed capture slot lands on it
    k_gemm<N_FEAT, N_HID, 8, 8, 0><<<(N_NODES + 127) / 128, 256>>>(x, W1, N_NODES);
    k_scan3<<<NBLK_SCAN, SCAN_B>>>();
    k_scatter<<<nblk_edges, TB>>>(ei, ew);

    k_agg<N_HID, 0><<<nblk_warp, TB>>>(b1, nullptr);
    k_gemm<N_HID, N_CLASS, 8, 4, 1><<<(N_NODES + 127) / 128, 256>>>(nullptr, W2, N_NODES);
    k_agg<N_CLASS, 1><<<nblk_warp, TB>>>(b2, out);
}

// round 7
// speedup vs baseline: 1.1505x; 1.0413x over previous
#include <cuda_runtime.h>
#include <cuda_fp16.h>
#include <cstdint>

#define N_NODES 50000
#define N_EDGES 1600000
#define N_FEAT  256
#define N_HID   128
#define N_CLASS 64

#define SCAN_B 1024
#define NBLK_SCAN ((N_NODES + SCAN_B - 1) / SCAN_B)   // 49

// ---------------- device scratch (static, no allocations) ----------------
// g_deg / g_cnt: zero at module load; every kernel_launch leaves them zeroed
// again (scan1 zeroes deg after reading, scan3 zeroes cnt after reading).
__device__ float g_deg[N_NODES];
__device__ float g_dinv[N_NODES];
__device__ int   g_cnt[N_NODES];
__device__ int   g_scan_tmp[N_NODES];
__device__ int   g_partials[64];
__device__ int   g_rowptr[N_NODES + 1];
__device__ int   g_loc[N_EDGES];            // per-edge local slot within its dest segment
__device__ int2  g_csr[N_EDGES];            // packed (src, __float_as_int(norm))
// intermediates: GEMM outputs stored fp16 (gather bandwidth), h kept fp32 (GEMM2 input)
__device__ half2  g_xwh[(size_t)N_NODES * (N_HID / 2)];    // x @ W1  [N,128] fp16
__device__ float4 g_h4 [(size_t)N_NODES * (N_HID / 4)];    // sigmoid(.) [N,128] fp32
__device__ half2  g_hwh[(size_t)N_NODES * (N_CLASS / 2)];  // h @ W2  [N,64] fp16

// ---------------- f32x2 packed-FMA helpers (sm_103a FFMA2, PTX-only) ----------------
__device__ __forceinline__ unsigned long long pack_dup(float a) {
    unsigned long long r;
    unsigned u = __float_as_uint(a);
    asm("mov.b64 %0, {%1, %1};" : "=l"(r) : "r"(u));
    return r;
}
__device__ __forceinline__ void fma2(unsigned long long& acc,
                                     unsigned long long a, unsigned long long b) {
    asm("fma.rn.f32x2 %0, %1, %2, %0;" : "+l"(acc) : "l"(a), "l"(b));
}
__device__ __forceinline__ float2 unpack2(unsigned long long v) {
    unsigned lo, hi;
    asm("mov.b64 {%0, %1}, %2;" : "=r"(lo), "=r"(hi) : "l"(v));
    return make_float2(__uint_as_float(lo), __uint_as_float(hi));
}

// ---------------- prep kernels ----------------
__global__ void k_deg(const int* __restrict__ ei, const float* __restrict__ ew) {
    int e = blockIdx.x * blockDim.x + threadIdx.x;
    if (e < N_EDGES) {
        int c = ei[N_EDGES + e];
        if ((unsigned)c < N_NODES) {
            atomicAdd(&g_deg[c], ew[e]);
            g_loc[e] = atomicAdd(&g_cnt[c], 1);
        }
    }
}

__global__ void k_scan1() {   // block-inclusive scan of cnt; dinv; self-clean deg
    __shared__ int s[SCAN_B];
    int i = blockIdx.x * SCAN_B + threadIdx.x;
    if (i < N_NODES) {
        float d = g_deg[i];
        g_dinv[i] = rsqrtf(d + 1.0f);   // +1 = self-loop weight
        g_deg[i] = 0.0f;                // restore invariant for next replay
    }
    int v = (i < N_NODES) ? g_cnt[i] : 0;
    s[threadIdx.x] = v;
    __syncthreads();
    for (int off = 1; off < SCAN_B; off <<= 1) {
        int t = (threadIdx.x >= off) ? s[threadIdx.x - off] : 0;
        __syncthreads();
        s[threadIdx.x] += t;
        __syncthreads();
    }
    if (i < N_NODES) g_scan_tmp[i] = s[threadIdx.x];      // inclusive
    if (threadIdx.x == SCAN_B - 1) g_partials[blockIdx.x] = s[SCAN_B - 1];
}

__global__ void k_scan2() {
    __shared__ int s[64];
    int t = threadIdx.x;
    int v = (t < NBLK_SCAN) ? g_partials[t] : 0;
    s[t] = v;
    __syncthreads();
    for (int off = 1; off < 64; off <<= 1) {
        int u = (t >= off) ? s[t - off] : 0;
        __syncthreads();
        s[t] += u;
        __syncthreads();
    }
    if (t < NBLK_SCAN) g_partials[t] = s[t] - v;          // exclusive
}

__global__ void k_scan3() {
    int i = blockIdx.x * SCAN_B + threadIdx.x;
    if (i < N_NODES) {
        g_rowptr[i] = g_scan_tmp[i] - g_cnt[i] + g_partials[blockIdx.x];
        g_cnt[i] = 0;                   // restore invariant for next replay
    }
    if (i == 0) g_rowptr[N_NODES] = N_EDGES;
}

__global__ void k_scatter(const int* __restrict__ ei, const float* __restrict__ ew) {
    int e = blockIdx.x * blockDim.x + threadIdx.x;
    if (e < N_EDGES) {
        int r = ei[e];
        int c = ei[N_EDGES + e];
        if ((unsigned)r < N_NODES && (unsigned)c < N_NODES) {
            float nrm = g_dinv[r] * ew[e] * g_dinv[c];
            int p = g_rowptr[c] + g_loc[e];          // atomic-free placement
            g_csr[p] = make_int2(r, __float_as_int(nrm));
        }
    }
}

// ---------------- f32x2-packed register-tiled GEMM, fp16 epilogue ----------------
// Thread handles TG groups of 4 contiguous columns (group g at col g*NO/2 + tx*4),
// so every B smem fetch is a float4 at 16B lane stride -> conflict-free LDS.128.
// LAYER 0: g_xwh = x(param) @ W1   (K=256, NO=128, TM=8, TG=2)
// LAYER 1: g_hwh = g_h @ W2        (K=128, NO=64,  TM=8, TG=1)
template<int K, int NO, int TM, int TN, int LAYER>
__global__ __launch_bounds__(256) void k_gemm(const float* __restrict__ Ain,
                                              const float* __restrict__ B, int M) {
    const float* __restrict__ A = (LAYER == 0) ? Ain : (const float*)g_h4;
    half2* __restrict__ C = (LAYER == 0) ? g_xwh : g_hwh;

    constexpr int BK = 16;
    constexpr int NX = NO / TN;              // 16 column groups
    constexpr int NY = 256 / NX;             // 16 row groups
    constexpr int BM = NY * TM;              // 128
    constexpr int TG = TN / 4;               // 4-col groups per thread (2 or 1)
    constexpr int CNT_A = BM * BK / (4 * 256);   // float4 A-loads per thread (=2)
    constexpr int CNT_B = BK * NO / (4 * 256);   // float4 B-loads per thread (2 or 1)

    __shared__ float As[BK][BM];             // A tile, transposed
    __shared__ float Bs[BK][NO];

    const int tid = threadIdx.x;
    const int bm  = blockIdx.x * BM;
    const int tx  = tid % NX;
    const int ty  = tid / NX;

    unsigned long long acc[TM][TG][2];
    #pragma unroll
    for (int i = 0; i < TM; i++)
        #pragma unroll
        for (int g = 0; g < TG; g++) { acc[i][g][0] = 0ull; acc[i][g][1] = 0ull; }

    for (int k0 = 0; k0 < K; k0 += BK) {
        #pragma unroll
        for (int i = 0; i < CNT_A; i++) {
            int t  = tid + i * 256;
            int r  = t >> 2;
            int c4 = (t & 3) << 2;
            float4 v = make_float4(0.f, 0.f, 0.f, 0.f);
            if (bm + r < M)
                v = *(const float4*)(A + (size_t)(bm + r) * K + k0 + c4);
            As[c4 + 0][r] = v.x; As[c4 + 1][r] = v.y;
            As[c4 + 2][r] = v.z; As[c4 + 3][r] = v.w;
        }
        #pragma unroll
        for (int i = 0; i < CNT_B; i++) {
            int t  = tid + i * 256;
            int r  = t / (NO / 4);
            int c4 = (t % (NO / 4)) << 2;
            *(float4*)&Bs[r][c4] = *(const float4*)(B + (size_t)(k0 + r) * NO + c4);
        }
        __syncthreads();

        #pragma unroll
        for (int k = 0; k < BK; k++) {
            // A: TM values, each duplicated into a 64-bit pair
            unsigned long long ap[TM];
            #pragma unroll
            for (int i = 0; i < TM; i += 4) {
                float4 a4 = *(const float4*)&As[k][ty * TM + i];
                ap[i]   = pack_dup(a4.x);
                ap[i+1] = pack_dup(a4.y);
                ap[i+2] = pack_dup(a4.z);
                ap[i+3] = pack_dup(a4.w);
            }
            // B: per group one contiguous float4 (16B lane stride, conflict-free)
            unsigned long long bp[TG][2];
            #pragma unroll
            for (int g = 0; g < TG; g++) {
                ulonglong2 b2 = *(const ulonglong2*)&Bs[k][g * (NO / 2) + tx * 4];
                bp[g][0] = b2.x;
                bp[g][1] = b2.y;
            }
            #pragma unroll
            for (int i = 0; i < TM; i++)
                #pragma unroll
                for (int g = 0; g < TG; g++) {
                    fma2(acc[i][g][0], ap[i], bp[g][0]);
                    fma2(acc[i][g][1], ap[i], bp[g][1]);
                }
        }
        __syncthreads();
    }

    #pragma unroll
    for (int i = 0; i < TM; i++) {
        int r = bm + ty * TM + i;
        if (r < M) {
            #pragma unroll
            for (int g = 0; g < TG; g++) {
                float2 f0 = unpack2(acc[i][g][0]);
                float2 f1 = unpack2(acc[i][g][1]);
                half2 p0 = __floats2half2_rn(f0.x, f0.y);
                half2 p1 = __floats2half2_rn(f1.x, f1.y);
                uint2 u;
                u.x = *(unsigned*)&p0; u.y = *(unsigned*)&p1;
                *(uint2*)(C + (size_t)r * (NO / 2) + g * (NO / 4) + tx * 2) = u;
            }
        }
    }
}

// ---------------- gather-based aggregation (fp16 gather, fp32 accumulate) ----------------
template<int F, int LAYER>
__global__ __launch_bounds__(256) void k_agg(const float* __restrict__ bias,
                                             float* __restrict__ out_param) {
    int gw   = (blockIdx.x * blockDim.x + threadIdx.x) >> 5;
    int lane = threadIdx.x & 31;
    if (gw >= N_NODES) return;
    const int c = gw;
    const int e0 = g_rowptr[c];
    const int e1 = g_rowptr[c + 1];
    const int2* __restrict__ csr = g_csr;

    if constexpr (F == 128) {
        const uint2* __restrict__ hv = (const uint2*)g_xwh;
        float4 acc = make_float4(0.f, 0.f, 0.f, 0.f);
        int p = e0;
        for (; p + 4 <= e1; p += 4) {           // 4 independent gathers in flight
            int2 s0 = csr[p], s1 = csr[p+1], s2 = csr[p+2], s3 = csr[p+3];
            uint2 q0 = hv[(size_t)s0.x * 32 + lane];
            uint2 q1 = hv[(size_t)s1.x * 32 + lane];
            uint2 q2 = hv[(size_t)s2.x * 32 + lane];
            uint2 q3 = hv[(size_t)s3.x * 32 + lane];
            float w0 = __int_as_float(s0.y), w1 = __int_as_float(s1.y);
            float w2 = __int_as_float(s2.y), w3 = __int_as_float(s3.y);
            float2 a0 = __half22float2(*(half2*)&q0.x), b0 = __half22float2(*(half2*)&q0.y);
            float2 a1 = __half22float2(*(half2*)&q1.x), b1 = __half22float2(*(half2*)&q1.y);
            float2 a2 = __half22float2(*(half2*)&q2.x), b2 = __half22float2(*(half2*)&q2.y);
            float2 a3 = __half22float2(*(half2*)&q3.x), b3 = __half22float2(*(half2*)&q3.y);
            acc.x = fmaf(w0, a0.x, acc.x); acc.y = fmaf(w0, a0.y, acc.y);
            acc.z = fmaf(w0, b0.x, acc.z); acc.w = fmaf(w0, b0.y, acc.w);
            acc.x = fmaf(w1, a1.x, acc.x); acc.y = fmaf(w1, a1.y, acc.y);
            acc.z = fmaf(w1, b1.x, acc.z); acc.w = fmaf(w1, b1.y, acc.w);
            acc.x = fmaf(w2, a2.x, acc.x); acc.y = fmaf(w2, a2.y, acc.y);
            acc.z = fmaf(w2, b2.x, acc.z); acc.w = fmaf(w2, b2.y, acc.w);
            acc.x = fmaf(w3, a3.x, acc.x); acc.y = fmaf(w3, a3.y, acc.y);
            acc.z = fmaf(w3, b3.x, acc.z); acc.w = fmaf(w3, b3.y, acc.w);
        }
        for (; p < e1; p++) {
            int2 s = csr[p];
            float w = __int_as_float(s.y);
            uint2 q = hv[(size_t)s.x * 32 + lane];
            float2 a = __half22float2(*(half2*)&q.x), b = __half22float2(*(half2*)&q.y);
            acc.x = fmaf(w, a.x, acc.x); acc.y = fmaf(w, a.y, acc.y);
            acc.z = fmaf(w, b.x, acc.z); acc.w = fmaf(w, b.y, acc.w);
        }
        float di = g_dinv[c];
        float sw = di * di;
        uint2 q = hv[(size_t)c * 32 + lane];
        float2 a = __half22float2(*(half2*)&q.x), b = __half22float2(*(half2*)&q.y);
        acc.x = fmaf(sw, a.x, acc.x); acc.y = fmaf(sw, a.y, acc.y);
        acc.z = fmaf(sw, b.x, acc.z); acc.w = fmaf(sw, b.y, acc.w);
        float4 bb = ((const float4*)bias)[lane];
        acc.x += bb.x; acc.y += bb.y; acc.z += bb.z; acc.w += bb.w;
        acc.x = 1.f / (1.f + __expf(-acc.x));
        acc.y = 1.f / (1.f + __expf(-acc.y));
        acc.z = 1.f / (1.f + __expf(-acc.z));
        acc.w = 1.f / (1.f + __expf(-acc.w));
        g_h4[(size_t)c * 32 + lane] = acc;      // fp32 for GEMM2 input
    } else {  // F == 64
        const unsigned* __restrict__ hv = (const unsigned*)g_hwh;
        float2 acc = make_float2(0.f, 0.f);
        int p = e0;
        for (; p + 4 <= e1; p += 4) {
            int2 s0 = csr[p], s1 = csr[p+1], s2 = csr[p+2], s3 = csr[p+3];
            unsigned q0 = hv[(size_t)s0.x * 32 + lane];
            unsigned q1 = hv[(size_t)s1.x * 32 + lane];
            unsigned q2 = hv[(size_t)s2.x * 32 + lane];
            unsigned q3 = hv[(size_t)s3.x * 32 + lane];
            float w0 = __int_as_float(s0.y), w1 = __int_as_float(s1.y);
            float w2 = __int_as_float(s2.y), w3 = __int_as_float(s3.y);
            float2 v0 = __half22float2(*(half2*)&q0);
            float2 v1 = __half22float2(*(half2*)&q1);
            float2 v2 = __half22float2(*(half2*)&q2);
            float2 v3 = __half22float2(*(half2*)&q3);
            acc.x = fmaf(w0, v0.x, acc.x); acc.y = fmaf(w0, v0.y, acc.y);
            acc.x = fmaf(w1, v1.x, acc.x); acc.y = fmaf(w1, v1.y, acc.y);
            acc.x = fmaf(w2, v2.x, acc.x); acc.y = fmaf(w2, v2.y, acc.y);
            acc.x = fmaf(w3, v3.x, acc.x); acc.y = fmaf(w3, v3.y, acc.y);
        }
        for (; p < e1; p++) {
            int2 s = csr[p];
            float w = __int_as_float(s.y);
            unsigned q = hv[(size_t)s.x * 32 + lane];
            float2 v = __half22float2(*(half2*)&q);
            acc.x = fmaf(w, v.x, acc.x);
            acc.y = fmaf(w, v.y, acc.y);
        }
        float di = g_dinv[c];
        float sw = di * di;
        unsigned q = hv[(size_t)c * 32 + lane];
        float2 v = __half22float2(*(half2*)&q);
        acc.x = fmaf(sw, v.x, acc.x);
        acc.y = fmaf(sw, v.y, acc.y);
        float2 bb = ((const float2*)bias)[lane];
        acc.x += bb.x; acc.y += bb.y;
        acc.x = tanhf(acc.x);
        acc.y = tanhf(acc.y);
        ((float2*)out_param)[(size_t)c * 32 + lane] = acc;
    }
}

// ---------------- launch ----------------
extern "C" void kernel_launch(void* const* d_in, const int* in_sizes, int n_in,
                              void* d_out, int out_size) {
    const float* x  = (const float*)d_in[0];
    const int*   ei = (const int*)d_in[1];     // int32 edge_index (2, E) row-major
    const float* ew = (const float*)d_in[2];
    const float* W1 = (const float*)d_in[3];
    const float* b1 = (const float*)d_in[4];
    const float* W2 = (const float*)d_in[5];
    const float* b2 = (const float*)d_in[6];
    float*       out = (float*)d_out;

    const int TB = 256;
    const int nblk_edges = (N_EDGES + TB - 1) / TB;       // 6250
    const int nblk_warp  = (N_NODES * 32 + TB - 1) / TB;  // 6250

    // prep (deg/cnt start zero: zero at load, re-zeroed by scan1/scan3 each call)
    k_deg  <<<nblk_edges, TB>>>(ei, ew);
    k_scan1<<<NBLK_SCAN, SCAN_B>>>();
    k_scan2<<<1, 64>>>();
    // gemm1 is independent of the CSR build; placed here so the profiler's
    // fixed capture slot lands on it
    k_gemm<N_FEAT, N_HID, 8, 8, 0><<<(N_NODES + 127) / 128, 256>>>(x, W1, N_NODES);
    k_scan3<<<NBLK_SCAN, SCAN_B>>>();
    k_scatter<<<nblk_edges, TB>>>(ei, ew);

    k_agg<N_HID, 0><<<nblk_warp, TB>>>(b1, nullptr);
    k_gemm<N_HID, N_CLASS, 8, 4, 1><<<(N_NODES + 127) / 128, 256>>>(nullptr, W2, N_NODES);
    k_agg<N_CLASS, 1><<<nblk_warp, TB>>>(b2, out);
}